// round 15
// baseline (speedup 1.0000x reference)
#include <cuda_runtime.h>
#include <cuda_fp16.h>
#include <cstdint>
#include <math.h>

// Problem constants
#define Bb 8
#define Ll 1024
#define Ff 1024
#define Hh 16
#define Dd 64
#define MTOT (Bb * Ll)   // 8192
#define EPS 1e-6f

// ---------------------------------------------------------------------------
// Scratch (device globals: allocation-free rule)
// ---------------------------------------------------------------------------
__device__ float g_q[MTOT * Ff];
__device__ float g_k[MTOT * Ff];
__device__ float g_v[MTOT * Ff];
__device__ float2 g_vstat[MTOT];      // (mean, inv_std) for V rows
__device__ __half g_qh[MTOT * Ff];    // pre-GEMM q; reused as Q [B,H,L,D]
__device__ __half g_kvh[MTOT * Ff];   // pre-GEMM kv; reused as K [B,H,L,D]
__device__ __half g_vth[MTOT * Ff];   // V^T [B,H,D,L]
__device__ __half g_oh[MTOT * Ff];    // attention out [B,L,F]
__device__ __half g_maskh[Ll * Ll];   // mask as fp16
__device__ __half g_wh[4][Ff * Ff];   // W^T [N][K] fp16

// ---------------------------------------------------------------------------
// PTX helpers (sm_80+ portable)
// ---------------------------------------------------------------------------
__device__ __forceinline__ uint32_t smem_u32(const void* p) {
    uint32_t a;
    asm("{ .reg .u64 t; cvta.to.shared.u64 t, %1; cvt.u32.u64 %0, t; }"
        : "=r"(a) : "l"(p));
    return a;
}

__device__ __forceinline__ void ldsm4(uint32_t* r, uint32_t addr) {
    asm volatile("ldmatrix.sync.aligned.m8n8.x4.shared.b16 {%0,%1,%2,%3}, [%4];"
                 : "=r"(r[0]), "=r"(r[1]), "=r"(r[2]), "=r"(r[3]) : "r"(addr));
}

__device__ __forceinline__ void mma16816(float* c, const uint32_t* a, const uint32_t* b) {
    asm volatile(
        "mma.sync.aligned.m16n8k16.row.col.f32.f16.f16.f32 "
        "{%0,%1,%2,%3}, {%4,%5,%6,%7}, {%8,%9}, {%0,%1,%2,%3};"
        : "+f"(c[0]), "+f"(c[1]), "+f"(c[2]), "+f"(c[3])
        : "r"(a[0]), "r"(a[1]), "r"(a[2]), "r"(a[3]), "r"(b[0]), "r"(b[1]));
}

#define CP_ASYNC16(dst, src) \
    asm volatile("cp.async.cg.shared.global [%0], [%1], 16;" :: "r"(dst), "l"(src) : "memory")
#define CP_COMMIT() asm volatile("cp.async.commit_group;" ::: "memory")
#define CP_WAIT1()  asm volatile("cp.async.wait_group 1;" ::: "memory")

// ---------------------------------------------------------------------------
// fp32 -> fp16. z=0 q, z=1 kv.
// ---------------------------------------------------------------------------
__global__ __launch_bounds__(256)
void convert_hi2(const float* __restrict__ q, const float* __restrict__ kv,
                 __half* __restrict__ QH, __half* __restrict__ KVH) {
    const int z = blockIdx.y;
    const float* X = z ? kv : q;
    __half* H = z ? KVH : QH;
    int i = blockIdx.x * 256 + threadIdx.x;
    float4 v = ((const float4*)X)[i];
    __half2 ha = __floats2half2_rn(v.x, v.y);
    __half2 hb = __floats2half2_rn(v.z, v.w);
    uint2 hu;
    hu.x = *(uint32_t*)&ha; hu.y = *(uint32_t*)&hb;
    ((uint2*)H)[i] = hu;
}

// ---------------------------------------------------------------------------
// mask fp32 -> fp16
// ---------------------------------------------------------------------------
__global__ __launch_bounds__(256)
void convert_mask(const float* __restrict__ M, __half* __restrict__ MH) {
    int i = blockIdx.x * 256 + threadIdx.x;
    float4 v = ((const float4*)M)[i];
    __half2 ha = __floats2half2_rn(v.x, v.y);
    __half2 hb = __floats2half2_rn(v.z, v.w);
    uint2 hu;
    hu.x = *(uint32_t*)&ha; hu.y = *(uint32_t*)&hb;
    ((uint2*)MH)[i] = hu;
}

// ---------------------------------------------------------------------------
// Transpose all 4 weight matrices to fp16 [N][K].
// ---------------------------------------------------------------------------
__global__ __launch_bounds__(256)
void transpose_hi_all(const float* __restrict__ Wq, const float* __restrict__ Wk,
                      const float* __restrict__ Wv, const float* __restrict__ Wo) {
    __shared__ float t[32][33];
    const float* W;
    switch (blockIdx.z) {
        case 0: W = Wq; break;
        case 1: W = Wk; break;
        case 2: W = Wv; break;
        default: W = Wo; break;
    }
    __half* H = g_wh[blockIdx.z];

    const int tx = threadIdx.x, ty = threadIdx.y;
    const int x0 = blockIdx.x * 32;  // n
    const int y0 = blockIdx.y * 32;  // k
#pragma unroll
    for (int j = ty; j < 32; j += 8)
        t[j][tx] = W[(size_t)(y0 + j) * Ff + x0 + tx];
    __syncthreads();
#pragma unroll
    for (int j = ty; j < 32; j += 8)
        H[(size_t)(x0 + j) * Ff + y0 + tx] = __float2half(t[tx][j]);
}

// ---------------------------------------------------------------------------
// Pure fp16 GEMM, BK=64 2-stage: 64 MMAs per chunk vs 2 barriers (restores
// the 60%-tensor compute/overhead ratio of the 2-product loop).
// z-batched: z selects A, W plane, C. Used for ALL four projections.
// ---------------------------------------------------------------------------
#define ROWST64 72
#define MATST64 (128 * ROWST64)                 // 9216 halves
#define PSTAGE64 (2 * MATST64)                  // 18432 halves
#define GEMM1_SMEM_BYTES (2 * PSTAGE64 * 2)     // 73728 B

__device__ __forceinline__ void gemm_issue_64(
    const __half* __restrict__ Ah, const __half* __restrict__ Bh,
    int m0, int n0, int kc, uint32_t sstage, int tid) {
    const int k0 = kc * 64;
    const int row = tid >> 1;
    const int cb  = tid & 1;
    const __half* srcs[2] = {Ah, Bh};
#pragma unroll
    for (int mat = 0; mat < 2; mat++) {
        const int gr = ((mat == 0) ? m0 : n0) + row;
        const __half* srow = srcs[mat] + (size_t)gr * Ff + k0;
        const uint32_t drow = sstage + (uint32_t)(mat * MATST64 + row * ROWST64) * 2;
#pragma unroll
        for (int j = 0; j < 4; j++) {
            const int chunk = cb + j * 2;       // 0..7
            CP_ASYNC16(drow + chunk * 16, srow + chunk * 8);
        }
    }
}

__global__ __launch_bounds__(256, 2)
void gemm_1p(const __half* __restrict__ A0, const __half* __restrict__ A1,
             const __half* __restrict__ A2, const __half* __restrict__ W,
             int wbase,
             float* __restrict__ C0, float* __restrict__ C1, float* __restrict__ C2) {
    extern __shared__ __align__(16) __half sm[];
    const int z = blockIdx.z;
    const __half* Ah = (z == 0) ? A0 : (z == 1) ? A1 : A2;
    const __half* Bh = W + (size_t)(wbase + z) * Ff * Ff;
    float* C = (z == 0) ? C0 : (z == 1) ? C1 : C2;

    const int tid = threadIdx.x;
    const int lane = tid & 31;
    const int wid = tid >> 5;
    const int wm = (wid >> 2) * 64;
    const int wn = (wid & 3) * 32;
    const int m0 = blockIdx.y * 128;
    const int n0 = blockIdx.x * 128;
    const uint32_t sbase = smem_u32(sm);

    float acc[4][4][4];
#pragma unroll
    for (int i = 0; i < 4; i++)
#pragma unroll
        for (int j = 0; j < 4; j++)
#pragma unroll
            for (int r = 0; r < 4; r++) acc[i][j][r] = 0.f;

    gemm_issue_64(Ah, Bh, m0, n0, 0, sbase, tid);
    CP_COMMIT();
    gemm_issue_64(Ah, Bh, m0, n0, 1, sbase + PSTAGE64 * 2, tid);
    CP_COMMIT();

    const int a_row = (lane & 15);
    const int a_col = (lane >> 4) << 3;
    const int bq = lane >> 3;
    const int b_row = (lane & 7) + ((bq >> 1) << 3);
    const int b_col = (bq & 1) << 3;

    for (int kc = 0; kc < 16; kc++) {
        CP_WAIT1();
        __syncthreads();
        const uint32_t st = sbase + (uint32_t)((kc & 1) * PSTAGE64) * 2;
        const uint32_t sAh = st;
        const uint32_t sBh = st + MATST64 * 2;

#pragma unroll
        for (int kk = 0; kk < 4; kk++) {
            uint32_t ah[4][4], bh[4][2];
#pragma unroll
            for (int mi = 0; mi < 4; mi++) {
                uint32_t off = (uint32_t)((wm + mi * 16 + a_row) * ROWST64 + kk * 16 + a_col) * 2;
                ldsm4(ah[mi], sAh + off);
            }
#pragma unroll
            for (int g = 0; g < 2; g++) {
                uint32_t off = (uint32_t)((wn + g * 16 + b_row) * ROWST64 + kk * 16 + b_col) * 2;
                uint32_t r[4];
                ldsm4(r, sBh + off);
                bh[g * 2][0] = r[0]; bh[g * 2][1] = r[1];
                bh[g * 2 + 1][0] = r[2]; bh[g * 2 + 1][1] = r[3];
            }
#pragma unroll
            for (int mi = 0; mi < 4; mi++)
#pragma unroll
                for (int ni = 0; ni < 4; ni++)
                    mma16816(acc[mi][ni], ah[mi], bh[ni]);
        }
        __syncthreads();
        if (kc + 2 < 16)
            gemm_issue_64(Ah, Bh, m0, n0, kc + 2,
                          sbase + (uint32_t)((kc & 1) * PSTAGE64) * 2, tid);
        CP_COMMIT();
    }

    const int er = lane >> 2;
    const int ec = (lane & 3) * 2;
#pragma unroll
    for (int mi = 0; mi < 4; mi++) {
        const int r0 = m0 + wm + mi * 16 + er;
#pragma unroll
        for (int ni = 0; ni < 4; ni++) {
            const int c = n0 + wn + ni * 8 + ec;
            *(float2*)(C + (size_t)r0 * Ff + c) = make_float2(acc[mi][ni][0], acc[mi][ni][1]);
            *(float2*)(C + (size_t)(r0 + 8) * Ff + c) = make_float2(acc[mi][ni][2], acc[mi][ni][3]);
        }
    }
}

// ---------------------------------------------------------------------------
// LN batched: z=0 -> q LN+reshape (x0.125), z=1 -> k LN+reshape,
// z=2 -> v stats only.
// ---------------------------------------------------------------------------
__global__ __launch_bounds__(256)
void ln3(const float* __restrict__ xq, const float* __restrict__ xk,
         const float* __restrict__ xv,
         const float* __restrict__ sq, const float* __restrict__ bq,
         const float* __restrict__ sk, const float* __restrict__ bk,
         __half* __restrict__ QH, __half* __restrict__ KH,
         float2* __restrict__ vstat) {
    __shared__ float red[16];
    const int z = blockIdx.y;
    const int row = blockIdx.x;
    const int b = row >> 10, l = row & 1023;
    const int tid = threadIdx.x;
    const float* x = (z == 0) ? xq : (z == 1) ? xk : xv;
    const float* xr = x + (size_t)row * Ff;

    float4 v = *(const float4*)(xr + tid * 4);
    float s  = v.x + v.y + v.z + v.w;
    float sq2 = v.x * v.x + v.y * v.y + v.z * v.z + v.w * v.w;
#pragma unroll
    for (int o = 16; o > 0; o >>= 1) {
        s   += __shfl_xor_sync(0xffffffffu, s, o);
        sq2 += __shfl_xor_sync(0xffffffffu, sq2, o);
    }
    const int warp = tid >> 5, lane = tid & 31;
    if (lane == 0) { red[warp] = s; red[warp + 8] = sq2; }
    __syncthreads();
    float st = 0.f, sqt = 0.f;
#pragma unroll
    for (int w = 0; w < 8; w++) { st += red[w]; sqt += red[w + 8]; }

    const float mean = st * (1.0f / Ff);
    const float var  = sqt * (1.0f / Ff) - mean * mean;
    const float inv  = rsqrtf(var + EPS);

    if (z == 2) {
        if (tid == 0) vstat[row] = make_float2(mean, inv);
        return;
    }

    const float* scale = (z == 0) ? sq : sk;
    const float* bias  = (z == 0) ? bq : bk;
    const float qs = (z == 0) ? 0.125f : 1.0f;
    __half* OH = (z == 0) ? QH : KH;

    float4 sc = *(const float4*)(scale + tid * 4);
    float4 bi = *(const float4*)(bias + tid * 4);
    float y0 = ((v.x - mean) * inv * sc.x + bi.x) * qs;
    float y1 = ((v.y - mean) * inv * sc.y + bi.y) * qs;
    float y2 = ((v.z - mean) * inv * sc.z + bi.z) * qs;
    float y3 = ((v.w - mean) * inv * sc.w + bi.w) * qs;

    const int col = tid * 4;
    const int h = col >> 6, d = col & 63;
    const size_t o = (((size_t)b * Hh + h) * Ll + l) * Dd + d;
    __half2 ha = __floats2half2_rn(y0, y1);
    __half2 hb = __floats2half2_rn(y2, y3);
    uint2 hu;
    hu.x = *(uint32_t*)&ha; hu.y = *(uint32_t*)&hb;
    *(uint2*)(OH + o) = hu;
}

// ---------------------------------------------------------------------------
// V: apply LN (from stats) + transpose to fp16 [B,H,D,L].
// ---------------------------------------------------------------------------
__global__ __launch_bounds__(256)
void vtrans_ln(const float* __restrict__ V, const float2* __restrict__ vstat,
               const float* __restrict__ sv, const float* __restrict__ bv,
               __half* __restrict__ TH) {
    __shared__ float ts[64][65];
    const int bh = blockIdx.x;
    const int b = bh >> 4, h = bh & 15;
    const int l0 = blockIdx.y * 64;
    const int tid = threadIdx.x;
    {
        const int i = tid >> 2;
        const int c0 = (tid & 3) * 16;
        const float2 stv = vstat[b * Ll + l0 + i];
        const float* src = V + ((size_t)b * Ll + l0 + i) * Ff + h * Dd + c0;
        const float* gp = sv + h * Dd + c0;
        const float* bp = bv + h * Dd + c0;
#pragma unroll
        for (int j = 0; j < 4; j++) {
            float4 a = *(const float4*)(src + j * 4);
            float4 g = *(const float4*)(gp + j * 4);
            float4 be = *(const float4*)(bp + j * 4);
            ts[i][c0 + j * 4 + 0] = (a.x - stv.x) * stv.y * g.x + be.x;
            ts[i][c0 + j * 4 + 1] = (a.y - stv.x) * stv.y * g.y + be.y;
            ts[i][c0 + j * 4 + 2] = (a.z - stv.x) * stv.y * g.z + be.z;
            ts[i][c0 + j * 4 + 3] = (a.w - stv.x) * stv.y * g.w + be.w;
        }
    }
    __syncthreads();
    {
        const int d = tid >> 2;
        const int lc = (tid & 3) * 16;
        const size_t o = ((size_t)bh * Dd + d) * Ll + l0 + lc;
        __align__(16) __half hs[16];
#pragma unroll
        for (int j = 0; j < 16; j++)
            hs[j] = __float2half(ts[lc + j][d]);
        *(uint4*)(TH + o)     = *(uint4*)(hs);
        *(uint4*)(TH + o + 8) = *(uint4*)(hs + 8);
    }
}

// ---------------------------------------------------------------------------
// Flash attention (mma.sync). QK^T: fp16. PV: pah*vh + pal*vh.
// 2 smem tiles/stage (Kh, Vth). fp16 mask, fp16 output. (R13/R14 version)
// ---------------------------------------------------------------------------
#define FROWS 72
#define FTILE (64 * FROWS)
#define FSTAGE (2 * FTILE)
#define FLASH_SMEM (2 * FSTAGE * 2)

__device__ __forceinline__ void flash_issue(
    const __half* __restrict__ Kh, const __half* __restrict__ Vth,
    int bh, int k0, uint32_t st, int tid) {
    const int row = tid >> 2;
    const int ch = tid & 3;
    const size_t kb = ((size_t)bh * Ll + k0) * Dd;
    const size_t vb = ((size_t)bh * Dd) * Ll + k0;
#pragma unroll
    for (int s = 0; s < 2; s++) {
        const int c8 = ch + s * 4;
        const uint32_t so = (uint32_t)(row * FROWS + c8 * 8) * 2;
        CP_ASYNC16(st + 0 * FTILE * 2 + so, Kh + kb + (size_t)row * Dd + c8 * 8);
        CP_ASYNC16(st + 1 * FTILE * 2 + so, Vth + vb + (size_t)row * Ll + c8 * 8);
    }
}

__global__ __launch_bounds__(256, 2)
void flash_mma(const __half* __restrict__ Qh, const __half* __restrict__ Kh,
               const __half* __restrict__ Vth,
               const __half* __restrict__ maskh,
               __half* __restrict__ Oh) {
    extern __shared__ __align__(16) __half fsm[];
    const int tid = threadIdx.x;
    const int lane = tid & 31;
    const int wid = tid >> 5;
    const int q0 = blockIdx.x * 128;
    const int bh = blockIdx.y;
    const int b = bh >> 4, h = bh & 15;
    const uint32_t sbase = smem_u32(fsm);
    const int wr0 = q0 + wid * 16;
    const int er = lane >> 2;
    const int ec = (lane & 3) * 2;

    uint32_t qfh[4][4];
    {
        const size_t qb = (size_t)bh * Ll * Dd;
        const size_t r0 = qb + (size_t)(wr0 + er) * Dd;
        const size_t r1 = qb + (size_t)(wr0 + er + 8) * Dd;
#pragma unroll
        for (int kk = 0; kk < 4; kk++) {
            const int c0 = kk * 16 + ec, c1 = kk * 16 + ec + 8;
            qfh[kk][0] = *(const uint32_t*)(Qh + r0 + c0);
            qfh[kk][1] = *(const uint32_t*)(Qh + r1 + c0);
            qfh[kk][2] = *(const uint32_t*)(Qh + r0 + c1);
            qfh[kk][3] = *(const uint32_t*)(Qh + r1 + c1);
        }
    }

    float oacc[8][4];
#pragma unroll
    for (int i = 0; i < 8; i++)
#pragma unroll
        for (int j = 0; j < 4; j++) oacc[i][j] = 0.f;
    float lsum0 = 0.f, lsum1 = 0.f;

    flash_issue(Kh, Vth, bh, 0, sbase, tid);
    CP_COMMIT();
    flash_issue(Kh, Vth, bh, 64, sbase + FSTAGE * 2, tid);
    CP_COMMIT();

    const int bq = lane >> 3;
    const int b_row = (lane & 7) + ((bq >> 1) << 3);
    const int b_col = (bq & 1) << 3;

    for (int t = 0; t < 16; t++) {
        CP_WAIT1();
        __syncthreads();
        const uint32_t st = sbase + (uint32_t)((t & 1) * FSTAGE) * 2;
        const uint32_t sKh = st;
        const uint32_t sVh = st + FTILE * 2;

        float sc[8][4];
#pragma unroll
        for (int i = 0; i < 8; i++)
#pragma unroll
            for (int j = 0; j < 4; j++) sc[i][j] = 0.f;

#pragma unroll
        for (int kk = 0; kk < 4; kk++) {
#pragma unroll
            for (int g = 0; g < 4; g++) {
                const uint32_t off = (uint32_t)((g * 16 + b_row) * FROWS + kk * 16 + b_col) * 2;
                uint32_t rh[4];
                ldsm4(rh, sKh + off);
                mma16816(sc[2 * g],     qfh[kk], rh);
                mma16816(sc[2 * g + 1], qfh[kk], rh + 2);
            }
        }

        const int k0 = t * 64;
        uint32_t pah[4][4], pal[4][4];
        const __half* mr0 = maskh + (size_t)(wr0 + er) * Ll + k0 + ec;
        const __half* mr1 = mr0 + 8 * Ll;
#pragma unroll
        for (int ni = 0; ni < 8; ni++) {
            float2 m0 = __half22float2(*(const __half2*)(mr0 + ni * 8));
            float2 m1 = __half22float2(*(const __half2*)(mr1 + ni * 8));
            float p0 = __expf(sc[ni][0] + m0.x);
            float p1 = __expf(sc[ni][1] + m0.y);
            float p2 = __expf(sc[ni][2] + m1.x);
            float p3 = __expf(sc[ni][3] + m1.y);
            lsum0 += p0 + p1;
            lsum1 += p2 + p3;
            __half2 h01 = __floats2half2_rn(p0, p1);
            __half2 h23 = __floats2half2_rn(p2, p3);
            float2 f01 = __half22float2(h01);
            float2 f23 = __half22float2(h23);
            __half2 l01 = __floats2half2_rn(p0 - f01.x, p1 - f01.y);
            __half2 l23 = __floats2half2_rn(p2 - f23.x, p3 - f23.y);
            const int kc = ni >> 1, u = ni & 1;
            pah[kc][u * 2 + 0] = *(uint32_t*)&h01;
            pah[kc][u * 2 + 1] = *(uint32_t*)&h23;
            pal[kc][u * 2 + 0] = *(uint32_t*)&l01;
            pal[kc][u * 2 + 1] = *(uint32_t*)&l23;
        }

#pragma unroll
        for (int kc = 0; kc < 4; kc++) {
#pragma unroll
            for (int g = 0; g < 4; g++) {
                const uint32_t off = (uint32_t)((g * 16 + b_row) * FROWS + kc * 16 + b_col) * 2;
                uint32_t rh[4];
                ldsm4(rh, sVh + off);
                mma16816(oacc[2 * g],     pah[kc], rh);
                mma16816(oacc[2 * g + 1], pah[kc], rh + 2);
                mma16816(oacc[2 * g],     pal[kc], rh);
                mma16816(oacc[2 * g + 1], pal[kc], rh + 2);
            }
        }
        __syncthreads();
        if (t + 2 < 16)
            flash_issue(Kh, Vth, bh, (t + 2) * 64,
                        sbase + (uint32_t)((t & 1) * FSTAGE) * 2, tid);
        CP_COMMIT();
    }

    lsum0 += __shfl_xor_sync(0xffffffffu, lsum0, 1);
    lsum0 += __shfl_xor_sync(0xffffffffu, lsum0, 2);
    lsum1 += __shfl_xor_sync(0xffffffffu, lsum1, 1);
    lsum1 += __shfl_xor_sync(0xffffffffu, lsum1, 2);
    const float inv0 = 1.0f / lsum0;
    const float inv1 = 1.0f / lsum1;

    const size_t ob0 = ((size_t)b * Ll + wr0 + er) * Ff + h * Dd + ec;
    const size_t ob1 = ob0 + (size_t)8 * Ff;
#pragma unroll
    for (int ni = 0; ni < 8; ni++) {
        __half2 h01 = __floats2half2_rn(oacc[ni][0] * inv0, oacc[ni][1] * inv0);
        __half2 h23 = __floats2half2_rn(oacc[ni][2] * inv1, oacc[ni][3] * inv1);
        *(uint32_t*)(Oh + ob0 + ni * 8) = *(uint32_t*)&h01;
        *(uint32_t*)(Oh + ob1 + ni * 8) = *(uint32_t*)&h23;
    }
}

// ---------------------------------------------------------------------------
// Launch
// ---------------------------------------------------------------------------
extern "C" void kernel_launch(void* const* d_in, const int* in_sizes, int n_in,
                              void* d_out, int out_size) {
    const float* kv    = (const float*)d_in[0];
    const float* q     = (const float*)d_in[1];
    const float* mask  = (const float*)d_in[2];
    const float* Wq    = (const float*)d_in[3];
    const float* Wk    = (const float*)d_in[4];
    const float* Wv    = (const float*)d_in[5];
    const float* Wo    = (const float*)d_in[6];
    const float* lnq_s = (const float*)d_in[7];
    const float* lnq_b = (const float*)d_in[8];
    const float* lnk_s = (const float*)d_in[9];
    const float* lnk_b = (const float*)d_in[10];
    const float* lnv_s = (const float*)d_in[11];
    const float* lnv_b = (const float*)d_in[12];
    float* out = (float*)d_out;

    float *pq, *pk, *pv;
    float2* pvstat;
    __half *pqh, *pkvh, *pvth, *poh, *pmh, *pwh;
    cudaGetSymbolAddress((void**)&pq, g_q);
    cudaGetSymbolAddress((void**)&pk, g_k);
    cudaGetSymbolAddress((void**)&pv, g_v);
    cudaGetSymbolAddress((void**)&pvstat, g_vstat);
    cudaGetSymbolAddress((void**)&pqh, g_qh);
    cudaGetSymbolAddress((void**)&pkvh, g_kvh);
    cudaGetSymbolAddress((void**)&pvth, g_vth);
    cudaGetSymbolAddress((void**)&poh, g_oh);
    cudaGetSymbolAddress((void**)&pmh, g_maskh);
    cudaGetSymbolAddress((void**)&pwh, g_wh);

    cudaFuncSetAttribute(gemm_1p, cudaFuncAttributeMaxDynamicSharedMemorySize,
                         GEMM1_SMEM_BYTES);
    cudaFuncSetAttribute(flash_mma, cudaFuncAttributeMaxDynamicSharedMemorySize,
                         FLASH_SMEM);

    const int conv_blocks = (MTOT * Ff / 4) / 256;  // 8192

    // 0: q + kv to fp16
    convert_hi2<<<dim3(conv_blocks, 2), 256>>>(q, kv, pqh, pkvh);
    // 1: mask to fp16
    convert_mask<<<(Ll * Ll / 4) / 256, 256>>>(mask, pmh);
    // 2: transpose all weights to fp16
    transpose_hi_all<<<dim3(32, 32, 4), dim3(32, 8)>>>(Wq, Wk, Wv, Wo);
    // 3: QKV projections (fp16, BK=64, z-batched)
    gemm_1p<<<dim3(Ff / 128, MTOT / 128, 3), 256, GEMM1_SMEM_BYTES>>>(
        pqh, pkvh, pkvh, pwh, 0, pq, pk, pv);
    // 4: LN q/k (+reshape) and V stats
    ln3<<<dim3(MTOT, 3), 256>>>(pq, pk, pv, lnq_s, lnq_b, lnk_s, lnk_b,
                                pqh, pkvh, pvstat);
    // 5: V LN-apply + transpose
    vtrans_ln<<<dim3(Bb * Hh, Ll / 64), 256>>>(pv, pvstat, lnv_s, lnv_b, pvth);
    // 6: attention
    flash_mma<<<dim3(Ll / 128, Bb * Hh), 256, FLASH_SMEM>>>(
        pqh, pkvh, pvth, pmh, poh);
    // 7: output projection (same kernel, W index 3)
    gemm_1p<<<dim3(Ff / 128, MTOT / 128, 1), 256, GEMM1_SMEM_BYTES>>>(
        poh, poh, poh, pwh, 3, out, out, out);
}

// round 16
// speedup vs baseline: 1.1286x; 1.1286x over previous
#include <cuda_runtime.h>
#include <cuda_fp16.h>
#include <cstdint>
#include <math.h>

// Problem constants
#define Bb 8
#define Ll 1024
#define Ff 1024
#define Hh 16
#define Dd 64
#define MTOT (Bb * Ll)   // 8192
#define EPS 1e-6f

// ---------------------------------------------------------------------------
// Scratch (device globals: allocation-free rule)
// ---------------------------------------------------------------------------
__device__ float g_q[MTOT * Ff];
__device__ float g_k[MTOT * Ff];
__device__ float g_v[MTOT * Ff];
__device__ float2 g_vstat[MTOT];      // (mean, inv_std) for V rows
__device__ __half g_qh[MTOT * Ff];    // pre-GEMM q; reused as Q [B,H,L,D]
__device__ __half g_kvh[MTOT * Ff];   // pre-GEMM kv; reused as K [B,H,L,D]
__device__ __half g_vth[MTOT * Ff];   // V^T [B,H,D,L]
__device__ __half g_oh[MTOT * Ff];    // attention out [B,L,F]
__device__ __half g_maskh[Ll * Ll];   // mask as fp16
__device__ __half g_wh[4][Ff * Ff];   // W^T [N][K] fp16

// ---------------------------------------------------------------------------
// PTX helpers (sm_80+ portable)
// ---------------------------------------------------------------------------
__device__ __forceinline__ uint32_t smem_u32(const void* p) {
    uint32_t a;
    asm("{ .reg .u64 t; cvta.to.shared.u64 t, %1; cvt.u32.u64 %0, t; }"
        : "=r"(a) : "l"(p));
    return a;
}

__device__ __forceinline__ void ldsm4(uint32_t* r, uint32_t addr) {
    asm volatile("ldmatrix.sync.aligned.m8n8.x4.shared.b16 {%0,%1,%2,%3}, [%4];"
                 : "=r"(r[0]), "=r"(r[1]), "=r"(r[2]), "=r"(r[3]) : "r"(addr));
}

__device__ __forceinline__ void mma16816(float* c, const uint32_t* a, const uint32_t* b) {
    asm volatile(
        "mma.sync.aligned.m16n8k16.row.col.f32.f16.f16.f32 "
        "{%0,%1,%2,%3}, {%4,%5,%6,%7}, {%8,%9}, {%0,%1,%2,%3};"
        : "+f"(c[0]), "+f"(c[1]), "+f"(c[2]), "+f"(c[3])
        : "r"(a[0]), "r"(a[1]), "r"(a[2]), "r"(a[3]), "r"(b[0]), "r"(b[1]));
}

#define CP_ASYNC16(dst, src) \
    asm volatile("cp.async.cg.shared.global [%0], [%1], 16;" :: "r"(dst), "l"(src) : "memory")
#define CP_COMMIT() asm volatile("cp.async.commit_group;" ::: "memory")
#define CP_WAIT1()  asm volatile("cp.async.wait_group 1;" ::: "memory")
#define CP_WAIT2()  asm volatile("cp.async.wait_group 2;" ::: "memory")

// ---------------------------------------------------------------------------
// fp32 -> fp16. z=0 q, z=1 kv.
// ---------------------------------------------------------------------------
__global__ __launch_bounds__(256)
void convert_hi2(const float* __restrict__ q, const float* __restrict__ kv,
                 __half* __restrict__ QH, __half* __restrict__ KVH) {
    const int z = blockIdx.y;
    const float* X = z ? kv : q;
    __half* H = z ? KVH : QH;
    int i = blockIdx.x * 256 + threadIdx.x;
    float4 v = ((const float4*)X)[i];
    __half2 ha = __floats2half2_rn(v.x, v.y);
    __half2 hb = __floats2half2_rn(v.z, v.w);
    uint2 hu;
    hu.x = *(uint32_t*)&ha; hu.y = *(uint32_t*)&hb;
    ((uint2*)H)[i] = hu;
}

// ---------------------------------------------------------------------------
// mask fp32 -> fp16
// ---------------------------------------------------------------------------
__global__ __launch_bounds__(256)
void convert_mask(const float* __restrict__ M, __half* __restrict__ MH) {
    int i = blockIdx.x * 256 + threadIdx.x;
    float4 v = ((const float4*)M)[i];
    __half2 ha = __floats2half2_rn(v.x, v.y);
    __half2 hb = __floats2half2_rn(v.z, v.w);
    uint2 hu;
    hu.x = *(uint32_t*)&ha; hu.y = *(uint32_t*)&hb;
    ((uint2*)MH)[i] = hu;
}

// ---------------------------------------------------------------------------
// Transpose all 4 weight matrices to fp16 [N][K].
// ---------------------------------------------------------------------------
__global__ __launch_bounds__(256)
void transpose_hi_all(const float* __restrict__ Wq, const float* __restrict__ Wk,
                      const float* __restrict__ Wv, const float* __restrict__ Wo) {
    __shared__ float t[32][33];
    const float* W;
    switch (blockIdx.z) {
        case 0: W = Wq; break;
        case 1: W = Wk; break;
        case 2: W = Wv; break;
        default: W = Wo; break;
    }
    __half* H = g_wh[blockIdx.z];

    const int tx = threadIdx.x, ty = threadIdx.y;
    const int x0 = blockIdx.x * 32;  // n
    const int y0 = blockIdx.y * 32;  // k
#pragma unroll
    for (int j = ty; j < 32; j += 8)
        t[j][tx] = W[(size_t)(y0 + j) * Ff + x0 + tx];
    __syncthreads();
#pragma unroll
    for (int j = ty; j < 32; j += 8)
        H[(size_t)(x0 + j) * Ff + y0 + tx] = __float2half(t[tx][j]);
}

// ---------------------------------------------------------------------------
// Pure fp16 GEMM: proven BK=32 sub-chunks (ROWST=40 layout, 4-thr/row issue),
// processed TWO per barrier via 4 sub-buffers => 64 MMAs per barrier pair.
// z-batched: z selects A, W plane, C. Used for ALL four projections.
// ---------------------------------------------------------------------------
#define ROWST 40
#define MATST (128 * ROWST)
#define PSTAGE (2 * MATST)                       // one BK=32 sub-chunk: Ah, Bh
#define GEMM1_SMEM_BYTES (4 * PSTAGE * 2)        // 81920 B (4 sub-buffers)

__device__ __forceinline__ void gemm_issue_1(
    const __half* __restrict__ Ah, const __half* __restrict__ Bh,
    int m0, int n0, int kc, uint32_t sstage, int tid) {
    const int k0 = kc * 32;
    const int row = tid >> 2;
    const int ch  = tid & 3;
    const __half* srcs[2] = {Ah, Bh};
#pragma unroll
    for (int j = 0; j < 4; j++) {
        const int mat = j >> 1;
        const int r = row + ((j & 1) << 6);
        const int gr = ((mat == 0) ? m0 : n0) + r;
        const __half* src = srcs[mat] + (size_t)gr * Ff + k0 + ch * 8;
        uint32_t dst = sstage + (uint32_t)(mat * MATST + r * ROWST + ch * 8) * 2;
        CP_ASYNC16(dst, src);
    }
}

__global__ __launch_bounds__(256, 2)
void gemm_1p(const __half* __restrict__ A0, const __half* __restrict__ A1,
             const __half* __restrict__ A2, const __half* __restrict__ W,
             int wbase,
             float* __restrict__ C0, float* __restrict__ C1, float* __restrict__ C2) {
    extern __shared__ __align__(16) __half sm[];
    const int z = blockIdx.z;
    const __half* Ah = (z == 0) ? A0 : (z == 1) ? A1 : A2;
    const __half* Bh = W + (size_t)(wbase + z) * Ff * Ff;
    float* C = (z == 0) ? C0 : (z == 1) ? C1 : C2;

    const int tid = threadIdx.x;
    const int lane = tid & 31;
    const int wid = tid >> 5;
    const int wm = (wid >> 2) * 64;
    const int wn = (wid & 3) * 32;
    const int m0 = blockIdx.y * 128;
    const int n0 = blockIdx.x * 128;
    const uint32_t sbase = smem_u32(sm);

    float acc[4][4][4];
#pragma unroll
    for (int i = 0; i < 4; i++)
#pragma unroll
        for (int j = 0; j < 4; j++)
#pragma unroll
            for (int r = 0; r < 4; r++) acc[i][j][r] = 0.f;

    // prologue: 4 sub-chunks in flight (one commit group each)
#pragma unroll
    for (int s = 0; s < 4; s++) {
        gemm_issue_1(Ah, Bh, m0, n0, s, sbase + (uint32_t)s * PSTAGE * 2, tid);
        CP_COMMIT();
    }

    const int a_row = (lane & 15);
    const int a_col = (lane >> 4) << 3;
    const int bq = lane >> 3;
    const int b_row = (lane & 7) + ((bq >> 1) << 3);
    const int b_col = (bq & 1) << 3;

    for (int kc2 = 0; kc2 < 16; kc2++) {
        CP_WAIT2();          // sub-chunks 2*kc2, 2*kc2+1 landed
        __syncthreads();

#pragma unroll
        for (int half = 0; half < 2; half++) {
            const int sub = 2 * kc2 + half;
            const uint32_t st = sbase + (uint32_t)((sub & 3) * PSTAGE) * 2;
            const uint32_t sAh = st;
            const uint32_t sBh = st + MATST * 2;

#pragma unroll
            for (int kk = 0; kk < 2; kk++) {
                uint32_t ah[4][4], bh[4][2];
#pragma unroll
                for (int mi = 0; mi < 4; mi++) {
                    uint32_t off = (uint32_t)((wm + mi * 16 + a_row) * ROWST + kk * 16 + a_col) * 2;
                    ldsm4(ah[mi], sAh + off);
                }
#pragma unroll
                for (int g = 0; g < 2; g++) {
                    uint32_t off = (uint32_t)((wn + g * 16 + b_row) * ROWST + kk * 16 + b_col) * 2;
                    uint32_t r[4];
                    ldsm4(r, sBh + off);
                    bh[g * 2][0] = r[0]; bh[g * 2][1] = r[1];
                    bh[g * 2 + 1][0] = r[2]; bh[g * 2 + 1][1] = r[3];
                }
#pragma unroll
                for (int mi = 0; mi < 4; mi++)
#pragma unroll
                    for (int ni = 0; ni < 4; ni++)
                        mma16816(acc[mi][ni], ah[mi], bh[ni]);
            }
        }
        __syncthreads();
        // refill the two buffers just consumed
#pragma unroll
        for (int half = 0; half < 2; half++) {
            const int sub = 2 * kc2 + 4 + half;
            if (sub < 32)
                gemm_issue_1(Ah, Bh, m0, n0, sub,
                             sbase + (uint32_t)((sub & 3) * PSTAGE) * 2, tid);
            CP_COMMIT();
        }
    }

    const int er = lane >> 2;
    const int ec = (lane & 3) * 2;
#pragma unroll
    for (int mi = 0; mi < 4; mi++) {
        const int r0 = m0 + wm + mi * 16 + er;
#pragma unroll
        for (int ni = 0; ni < 4; ni++) {
            const int c = n0 + wn + ni * 8 + ec;
            *(float2*)(C + (size_t)r0 * Ff + c) = make_float2(acc[mi][ni][0], acc[mi][ni][1]);
            *(float2*)(C + (size_t)(r0 + 8) * Ff + c) = make_float2(acc[mi][ni][2], acc[mi][ni][3]);
        }
    }
}

// ---------------------------------------------------------------------------
// LN batched: z=0 -> q LN+reshape (x0.125), z=1 -> k LN+reshape,
// z=2 -> v stats only.
// ---------------------------------------------------------------------------
__global__ __launch_bounds__(256)
void ln3(const float* __restrict__ xq, const float* __restrict__ xk,
         const float* __restrict__ xv,
         const float* __restrict__ sq, const float* __restrict__ bq,
         const float* __restrict__ sk, const float* __restrict__ bk,
         __half* __restrict__ QH, __half* __restrict__ KH,
         float2* __restrict__ vstat) {
    __shared__ float red[16];
    const int z = blockIdx.y;
    const int row = blockIdx.x;
    const int b = row >> 10, l = row & 1023;
    const int tid = threadIdx.x;
    const float* x = (z == 0) ? xq : (z == 1) ? xk : xv;
    const float* xr = x + (size_t)row * Ff;

    float4 v = *(const float4*)(xr + tid * 4);
    float s  = v.x + v.y + v.z + v.w;
    float sq2 = v.x * v.x + v.y * v.y + v.z * v.z + v.w * v.w;
#pragma unroll
    for (int o = 16; o > 0; o >>= 1) {
        s   += __shfl_xor_sync(0xffffffffu, s, o);
        sq2 += __shfl_xor_sync(0xffffffffu, sq2, o);
    }
    const int warp = tid >> 5, lane = tid & 31;
    if (lane == 0) { red[warp] = s; red[warp + 8] = sq2; }
    __syncthreads();
    float st = 0.f, sqt = 0.f;
#pragma unroll
    for (int w = 0; w < 8; w++) { st += red[w]; sqt += red[w + 8]; }

    const float mean = st * (1.0f / Ff);
    const float var  = sqt * (1.0f / Ff) - mean * mean;
    const float inv  = rsqrtf(var + EPS);

    if (z == 2) {
        if (tid == 0) vstat[row] = make_float2(mean, inv);
        return;
    }

    const float* scale = (z == 0) ? sq : sk;
    const float* bias  = (z == 0) ? bq : bk;
    const float qs = (z == 0) ? 0.125f : 1.0f;
    __half* OH = (z == 0) ? QH : KH;

    float4 sc = *(const float4*)(scale + tid * 4);
    float4 bi = *(const float4*)(bias + tid * 4);
    float y0 = ((v.x - mean) * inv * sc.x + bi.x) * qs;
    float y1 = ((v.y - mean) * inv * sc.y + bi.y) * qs;
    float y2 = ((v.z - mean) * inv * sc.z + bi.z) * qs;
    float y3 = ((v.w - mean) * inv * sc.w + bi.w) * qs;

    const int col = tid * 4;
    const int h = col >> 6, d = col & 63;
    const size_t o = (((size_t)b * Hh + h) * Ll + l) * Dd + d;
    __half2 ha = __floats2half2_rn(y0, y1);
    __half2 hb = __floats2half2_rn(y2, y3);
    uint2 hu;
    hu.x = *(uint32_t*)&ha; hu.y = *(uint32_t*)&hb;
    *(uint2*)(OH + o) = hu;
}

// ---------------------------------------------------------------------------
// V: apply LN (from stats) + transpose to fp16 [B,H,D,L].
// ---------------------------------------------------------------------------
__global__ __launch_bounds__(256)
void vtrans_ln(const float* __restrict__ V, const float2* __restrict__ vstat,
               const float* __restrict__ sv, const float* __restrict__ bv,
               __half* __restrict__ TH) {
    __shared__ float ts[64][65];
    const int bh = blockIdx.x;
    const int b = bh >> 4, h = bh & 15;
    const int l0 = blockIdx.y * 64;
    const int tid = threadIdx.x;
    {
        const int i = tid >> 2;
        const int c0 = (tid & 3) * 16;
        const float2 stv = vstat[b * Ll + l0 + i];
        const float* src = V + ((size_t)b * Ll + l0 + i) * Ff + h * Dd + c0;
        const float* gp = sv + h * Dd + c0;
        const float* bp = bv + h * Dd + c0;
#pragma unroll
        for (int j = 0; j < 4; j++) {
            float4 a = *(const float4*)(src + j * 4);
            float4 g = *(const float4*)(gp + j * 4);
            float4 be = *(const float4*)(bp + j * 4);
            ts[i][c0 + j * 4 + 0] = (a.x - stv.x) * stv.y * g.x + be.x;
            ts[i][c0 + j * 4 + 1] = (a.y - stv.x) * stv.y * g.y + be.y;
            ts[i][c0 + j * 4 + 2] = (a.z - stv.x) * stv.y * g.z + be.z;
            ts[i][c0 + j * 4 + 3] = (a.w - stv.x) * stv.y * g.w + be.w;
        }
    }
    __syncthreads();
    {
        const int d = tid >> 2;
        const int lc = (tid & 3) * 16;
        const size_t o = ((size_t)bh * Dd + d) * Ll + l0 + lc;
        __align__(16) __half hs[16];
#pragma unroll
        for (int j = 0; j < 16; j++)
            hs[j] = __float2half(ts[lc + j][d]);
        *(uint4*)(TH + o)     = *(uint4*)(hs);
        *(uint4*)(TH + o + 8) = *(uint4*)(hs + 8);
    }
}

// ---------------------------------------------------------------------------
// Flash attention (mma.sync). QK^T: fp16. PV: pah*vh + pal*vh.
// 2 smem tiles/stage (Kh, Vth). fp16 mask, fp16 output. (R14 version)
// ---------------------------------------------------------------------------
#define FROWS 72
#define FTILE (64 * FROWS)
#define FSTAGE (2 * FTILE)
#define FLASH_SMEM (2 * FSTAGE * 2)

__device__ __forceinline__ void flash_issue(
    const __half* __restrict__ Kh, const __half* __restrict__ Vth,
    int bh, int k0, uint32_t st, int tid) {
    const int row = tid >> 2;
    const int ch = tid & 3;
    const size_t kb = ((size_t)bh * Ll + k0) * Dd;
    const size_t vb = ((size_t)bh * Dd) * Ll + k0;
#pragma unroll
    for (int s = 0; s < 2; s++) {
        const int c8 = ch + s * 4;
        const uint32_t so = (uint32_t)(row * FROWS + c8 * 8) * 2;
        CP_ASYNC16(st + 0 * FTILE * 2 + so, Kh + kb + (size_t)row * Dd + c8 * 8);
        CP_ASYNC16(st + 1 * FTILE * 2 + so, Vth + vb + (size_t)row * Ll + c8 * 8);
    }
}

__global__ __launch_bounds__(256, 2)
void flash_mma(const __half* __restrict__ Qh, const __half* __restrict__ Kh,
               const __half* __restrict__ Vth,
               const __half* __restrict__ maskh,
               __half* __restrict__ Oh) {
    extern __shared__ __align__(16) __half fsm[];
    const int tid = threadIdx.x;
    const int lane = tid & 31;
    const int wid = tid >> 5;
    const int q0 = blockIdx.x * 128;
    const int bh = blockIdx.y;
    const int b = bh >> 4, h = bh & 15;
    const uint32_t sbase = smem_u32(fsm);
    const int wr0 = q0 + wid * 16;
    const int er = lane >> 2;
    const int ec = (lane & 3) * 2;

    uint32_t qfh[4][4];
    {
        const size_t qb = (size_t)bh * Ll * Dd;
        const size_t r0 = qb + (size_t)(wr0 + er) * Dd;
        const size_t r1 = qb + (size_t)(wr0 + er + 8) * Dd;
#pragma unroll
        for (int kk = 0; kk < 4; kk++) {
            const int c0 = kk * 16 + ec, c1 = kk * 16 + ec + 8;
            qfh[kk][0] = *(const uint32_t*)(Qh + r0 + c0);
            qfh[kk][1] = *(const uint32_t*)(Qh + r1 + c0);
            qfh[kk][2] = *(const uint32_t*)(Qh + r0 + c1);
            qfh[kk][3] = *(const uint32_t*)(Qh + r1 + c1);
        }
    }

    float oacc[8][4];
#pragma unroll
    for (int i = 0; i < 8; i++)
#pragma unroll
        for (int j = 0; j < 4; j++) oacc[i][j] = 0.f;
    float lsum0 = 0.f, lsum1 = 0.f;

    flash_issue(Kh, Vth, bh, 0, sbase, tid);
    CP_COMMIT();
    flash_issue(Kh, Vth, bh, 64, sbase + FSTAGE * 2, tid);
    CP_COMMIT();

    const int bq = lane >> 3;
    const int b_row = (lane & 7) + ((bq >> 1) << 3);
    const int b_col = (bq & 1) << 3;

    for (int t = 0; t < 16; t++) {
        CP_WAIT1();
        __syncthreads();
        const uint32_t st = sbase + (uint32_t)((t & 1) * FSTAGE) * 2;
        const uint32_t sKh = st;
        const uint32_t sVh = st + FTILE * 2;

        float sc[8][4];
#pragma unroll
        for (int i = 0; i < 8; i++)
#pragma unroll
            for (int j = 0; j < 4; j++) sc[i][j] = 0.f;

#pragma unroll
        for (int kk = 0; kk < 4; kk++) {
#pragma unroll
            for (int g = 0; g < 4; g++) {
                const uint32_t off = (uint32_t)((g * 16 + b_row) * FROWS + kk * 16 + b_col) * 2;
                uint32_t rh[4];
                ldsm4(rh, sKh + off);
                mma16816(sc[2 * g],     qfh[kk], rh);
                mma16816(sc[2 * g + 1], qfh[kk], rh + 2);
            }
        }

        const int k0 = t * 64;
        uint32_t pah[4][4], pal[4][4];
        const __half* mr0 = maskh + (size_t)(wr0 + er) * Ll + k0 + ec;
        const __half* mr1 = mr0 + 8 * Ll;
#pragma unroll
        for (int ni = 0; ni < 8; ni++) {
            float2 m0 = __half22float2(*(const __half2*)(mr0 + ni * 8));
            float2 m1 = __half22float2(*(const __half2*)(mr1 + ni * 8));
            float p0 = __expf(sc[ni][0] + m0.x);
            float p1 = __expf(sc[ni][1] + m0.y);
            float p2 = __expf(sc[ni][2] + m1.x);
            float p3 = __expf(sc[ni][3] + m1.y);
            lsum0 += p0 + p1;
            lsum1 += p2 + p3;
            __half2 h01 = __floats2half2_rn(p0, p1);
            __half2 h23 = __floats2half2_rn(p2, p3);
            float2 f01 = __half22float2(h01);
            float2 f23 = __half22float2(h23);
            __half2 l01 = __floats2half2_rn(p0 - f01.x, p1 - f01.y);
            __half2 l23 = __floats2half2_rn(p2 - f23.x, p3 - f23.y);
            const int kc = ni >> 1, u = ni & 1;
            pah[kc][u * 2 + 0] = *(uint32_t*)&h01;
            pah[kc][u * 2 + 1] = *(uint32_t*)&h23;
            pal[kc][u * 2 + 0] = *(uint32_t*)&l01;
            pal[kc][u * 2 + 1] = *(uint32_t*)&l23;
        }

#pragma unroll
        for (int kc = 0; kc < 4; kc++) {
#pragma unroll
            for (int g = 0; g < 4; g++) {
                const uint32_t off = (uint32_t)((g * 16 + b_row) * FROWS + kc * 16 + b_col) * 2;
                uint32_t rh[4];
                ldsm4(rh, sVh + off);
                mma16816(oacc[2 * g],     pah[kc], rh);
                mma16816(oacc[2 * g + 1], pah[kc], rh + 2);
                mma16816(oacc[2 * g],     pal[kc], rh);
                mma16816(oacc[2 * g + 1], pal[kc], rh + 2);
            }
        }
        __syncthreads();
        if (t + 2 < 16)
            flash_issue(Kh, Vth, bh, (t + 2) * 64,
                        sbase + (uint32_t)((t & 1) * FSTAGE) * 2, tid);
        CP_COMMIT();
    }

    lsum0 += __shfl_xor_sync(0xffffffffu, lsum0, 1);
    lsum0 += __shfl_xor_sync(0xffffffffu, lsum0, 2);
    lsum1 += __shfl_xor_sync(0xffffffffu, lsum1, 1);
    lsum1 += __shfl_xor_sync(0xffffffffu, lsum1, 2);
    const float inv0 = 1.0f / lsum0;
    const float inv1 = 1.0f / lsum1;

    const size_t ob0 = ((size_t)b * Ll + wr0 + er) * Ff + h * Dd + ec;
    const size_t ob1 = ob0 + (size_t)8 * Ff;
#pragma unroll
    for (int ni = 0; ni < 8; ni++) {
        __half2 h01 = __floats2half2_rn(oacc[ni][0] * inv0, oacc[ni][1] * inv0);
        __half2 h23 = __floats2half2_rn(oacc[ni][2] * inv1, oacc[ni][3] * inv1);
        *(uint32_t*)(Oh + ob0 + ni * 8) = *(uint32_t*)&h01;
        *(uint32_t*)(Oh + ob1 + ni * 8) = *(uint32_t*)&h23;
    }
}

// ---------------------------------------------------------------------------
// Launch
// ---------------------------------------------------------------------------
extern "C" void kernel_launch(void* const* d_in, const int* in_sizes, int n_in,
                              void* d_out, int out_size) {
    const float* kv    = (const float*)d_in[0];
    const float* q     = (const float*)d_in[1];
    const float* mask  = (const float*)d_in[2];
    const float* Wq    = (const float*)d_in[3];
    const float* Wk    = (const float*)d_in[4];
    const float* Wv    = (const float*)d_in[5];
    const float* Wo    = (const float*)d_in[6];
    const float* lnq_s = (const float*)d_in[7];
    const float* lnq_b = (const float*)d_in[8];
    const float* lnk_s = (const float*)d_in[9];
    const float* lnk_b = (const float*)d_in[10];
    const float* lnv_s = (const float*)d_in[11];
    const float* lnv_b = (const float*)d_in[12];
    float* out = (float*)d_out;

    float *pq, *pk, *pv;
    float2* pvstat;
    __half *pqh, *pkvh, *pvth, *poh, *pmh, *pwh;
    cudaGetSymbolAddress((void**)&pq, g_q);
    cudaGetSymbolAddress((void**)&pk, g_k);
    cudaGetSymbolAddress((void**)&pv, g_v);
    cudaGetSymbolAddress((void**)&pvstat, g_vstat);
    cudaGetSymbolAddress((void**)&pqh, g_qh);
    cudaGetSymbolAddress((void**)&pkvh, g_kvh);
    cudaGetSymbolAddress((void**)&pvth, g_vth);
    cudaGetSymbolAddress((void**)&poh, g_oh);
    cudaGetSymbolAddress((void**)&pmh, g_maskh);
    cudaGetSymbolAddress((void**)&pwh, g_wh);

    cudaFuncSetAttribute(gemm_1p, cudaFuncAttributeMaxDynamicSharedMemorySize,
                         GEMM1_SMEM_BYTES);
    cudaFuncSetAttribute(flash_mma, cudaFuncAttributeMaxDynamicSharedMemorySize,
                         FLASH_SMEM);

    const int conv_blocks = (MTOT * Ff / 4) / 256;  // 8192

    // 0: q + kv to fp16
    convert_hi2<<<dim3(conv_blocks, 2), 256>>>(q, kv, pqh, pkvh);
    // 1: mask to fp16
    convert_mask<<<(Ll * Ll / 4) / 256, 256>>>(mask, pmh);
    // 2: transpose all weights to fp16
    transpose_hi_all<<<dim3(32, 32, 4), dim3(32, 8)>>>(Wq, Wk, Wv, Wo);
    // 3: QKV projections (fp16, 2 sub-chunks/barrier, z-batched)
    gemm_1p<<<dim3(Ff / 128, MTOT / 128, 3), 256, GEMM1_SMEM_BYTES>>>(
        pqh, pkvh, pkvh, pwh, 0, pq, pk, pv);
    // 4: LN q/k (+reshape) and V stats
    ln3<<<dim3(MTOT, 3), 256>>>(pq, pk, pv, lnq_s, lnq_b, lnk_s, lnk_b,
                                pqh, pkvh, pvstat);
    // 5: V LN-apply + transpose
    vtrans_ln<<<dim3(Bb * Hh, Ll / 64), 256>>>(pv, pvstat, lnv_s, lnv_b, pvth);
    // 6: attention
    flash_mma<<<dim3(Ll / 128, Bb * Hh), 256, FLASH_SMEM>>>(
        pqh, pkvh, pvth, pmh, poh);
    // 7: output projection (same kernel, W index 3)
    gemm_1p<<<dim3(Ff / 128, MTOT / 128, 1), 256, GEMM1_SMEM_BYTES>>>(
        poh, poh, poh, pwh, 3, out, out, out);
}

// round 17
// speedup vs baseline: 1.1471x; 1.0164x over previous
#include <cuda_runtime.h>
#include <cuda_fp16.h>
#include <cstdint>
#include <math.h>

// Problem constants
#define Bb 8
#define Ll 1024
#define Ff 1024
#define Hh 16
#define Dd 64
#define MTOT (Bb * Ll)   // 8192
#define EPS 1e-6f

// ---------------------------------------------------------------------------
// Scratch (device globals: allocation-free rule)
// ---------------------------------------------------------------------------
__device__ __half g_cq[MTOT * Ff];    // QKV gemm outputs (fp16, pre-LN)
__device__ __half g_ck[MTOT * Ff];
__device__ __half g_cv[MTOT * Ff];
__device__ float2 g_vstat[MTOT];      // (mean, inv_std) for V rows
__device__ __half g_qh[MTOT * Ff];    // pre-GEMM q; reused as Q [B,H,L,D]
__device__ __half g_kvh[MTOT * Ff];   // pre-GEMM kv; reused as K [B,H,L,D]
__device__ __half g_vth[MTOT * Ff];   // V^T [B,H,D,L]
__device__ __half g_oh[MTOT * Ff];    // attention out [B,L,F]
__device__ __half g_maskh[Ll * Ll];   // mask as fp16
__device__ __half g_wh[4][Ff * Ff];   // W^T [N][K] fp16

// ---------------------------------------------------------------------------
// PTX helpers (sm_80+ portable)
// ---------------------------------------------------------------------------
__device__ __forceinline__ uint32_t smem_u32(const void* p) {
    uint32_t a;
    asm("{ .reg .u64 t; cvta.to.shared.u64 t, %1; cvt.u32.u64 %0, t; }"
        : "=r"(a) : "l"(p));
    return a;
}

__device__ __forceinline__ void ldsm4(uint32_t* r, uint32_t addr) {
    asm volatile("ldmatrix.sync.aligned.m8n8.x4.shared.b16 {%0,%1,%2,%3}, [%4];"
                 : "=r"(r[0]), "=r"(r[1]), "=r"(r[2]), "=r"(r[3]) : "r"(addr));
}

__device__ __forceinline__ void mma16816(float* c, const uint32_t* a, const uint32_t* b) {
    asm volatile(
        "mma.sync.aligned.m16n8k16.row.col.f32.f16.f16.f32 "
        "{%0,%1,%2,%3}, {%4,%5,%6,%7}, {%8,%9}, {%0,%1,%2,%3};"
        : "+f"(c[0]), "+f"(c[1]), "+f"(c[2]), "+f"(c[3])
        : "r"(a[0]), "r"(a[1]), "r"(a[2]), "r"(a[3]), "r"(b[0]), "r"(b[1]));
}

#define CP_ASYNC16(dst, src) \
    asm volatile("cp.async.cg.shared.global [%0], [%1], 16;" :: "r"(dst), "l"(src) : "memory")
#define CP_COMMIT() asm volatile("cp.async.commit_group;" ::: "memory")
#define CP_WAIT1()  asm volatile("cp.async.wait_group 1;" ::: "memory")
#define CP_WAIT2()  asm volatile("cp.async.wait_group 2;" ::: "memory")

// ---------------------------------------------------------------------------
// fp32 -> fp16. z=0 q, z=1 kv.
// ---------------------------------------------------------------------------
__global__ __launch_bounds__(256)
void convert_hi2(const float* __restrict__ q, const float* __restrict__ kv,
                 __half* __restrict__ QH, __half* __restrict__ KVH) {
    const int z = blockIdx.y;
    const float* X = z ? kv : q;
    __half* H = z ? KVH : QH;
    int i = blockIdx.x * 256 + threadIdx.x;
    float4 v = ((const float4*)X)[i];
    __half2 ha = __floats2half2_rn(v.x, v.y);
    __half2 hb = __floats2half2_rn(v.z, v.w);
    uint2 hu;
    hu.x = *(uint32_t*)&ha; hu.y = *(uint32_t*)&hb;
    ((uint2*)H)[i] = hu;
}

// ---------------------------------------------------------------------------
// mask fp32 -> fp16
// ---------------------------------------------------------------------------
__global__ __launch_bounds__(256)
void convert_mask(const float* __restrict__ M, __half* __restrict__ MH) {
    int i = blockIdx.x * 256 + threadIdx.x;
    float4 v = ((const float4*)M)[i];
    __half2 ha = __floats2half2_rn(v.x, v.y);
    __half2 hb = __floats2half2_rn(v.z, v.w);
    uint2 hu;
    hu.x = *(uint32_t*)&ha; hu.y = *(uint32_t*)&hb;
    ((uint2*)MH)[i] = hu;
}

// ---------------------------------------------------------------------------
// Transpose all 4 weight matrices to fp16 [N][K].
// ---------------------------------------------------------------------------
__global__ __launch_bounds__(256)
void transpose_hi_all(const float* __restrict__ Wq, const float* __restrict__ Wk,
                      const float* __restrict__ Wv, const float* __restrict__ Wo) {
    __shared__ float t[32][33];
    const float* W;
    switch (blockIdx.z) {
        case 0: W = Wq; break;
        case 1: W = Wk; break;
        case 2: W = Wv; break;
        default: W = Wo; break;
    }
    __half* H = g_wh[blockIdx.z];

    const int tx = threadIdx.x, ty = threadIdx.y;
    const int x0 = blockIdx.x * 32;  // n
    const int y0 = blockIdx.y * 32;  // k
#pragma unroll
    for (int j = ty; j < 32; j += 8)
        t[j][tx] = W[(size_t)(y0 + j) * Ff + x0 + tx];
    __syncthreads();
#pragma unroll
    for (int j = ty; j < 32; j += 8)
        H[(size_t)(x0 + j) * Ff + y0 + tx] = __float2half(t[tx][j]);
}

// ---------------------------------------------------------------------------
// Pure fp16 GEMM: BK=32 sub-chunks (ROWST=40, 4-thr/row), 2 sub-chunks per
// barrier via 4 sub-buffers (R16 proven loop). Templated epilogue dtype:
// HOUT=true -> fp16 C (QKV intermediates), HOUT=false -> fp32 C (final out).
// ---------------------------------------------------------------------------
#define ROWST 40
#define MATST (128 * ROWST)
#define PSTAGE (2 * MATST)
#define GEMM1_SMEM_BYTES (4 * PSTAGE * 2)        // 81920 B

__device__ __forceinline__ void gemm_issue_1(
    const __half* __restrict__ Ah, const __half* __restrict__ Bh,
    int m0, int n0, int kc, uint32_t sstage, int tid) {
    const int k0 = kc * 32;
    const int row = tid >> 2;
    const int ch  = tid & 3;
    const __half* srcs[2] = {Ah, Bh};
#pragma unroll
    for (int j = 0; j < 4; j++) {
        const int mat = j >> 1;
        const int r = row + ((j & 1) << 6);
        const int gr = ((mat == 0) ? m0 : n0) + r;
        const __half* src = srcs[mat] + (size_t)gr * Ff + k0 + ch * 8;
        uint32_t dst = sstage + (uint32_t)(mat * MATST + r * ROWST + ch * 8) * 2;
        CP_ASYNC16(dst, src);
    }
}

template <bool HOUT>
__global__ __launch_bounds__(256, 2)
void gemm_1p(const __half* __restrict__ A0, const __half* __restrict__ A1,
             const __half* __restrict__ A2, const __half* __restrict__ W,
             int wbase,
             float* __restrict__ Cf,
             __half* __restrict__ H0, __half* __restrict__ H1,
             __half* __restrict__ H2) {
    extern __shared__ __align__(16) __half sm[];
    const int z = blockIdx.z;
    const __half* Ah = (z == 0) ? A0 : (z == 1) ? A1 : A2;
    const __half* Bh = W + (size_t)(wbase + z) * Ff * Ff;
    __half* Ch = (z == 0) ? H0 : (z == 1) ? H1 : H2;

    const int tid = threadIdx.x;
    const int lane = tid & 31;
    const int wid = tid >> 5;
    const int wm = (wid >> 2) * 64;
    const int wn = (wid & 3) * 32;
    const int m0 = blockIdx.y * 128;
    const int n0 = blockIdx.x * 128;
    const uint32_t sbase = smem_u32(sm);

    float acc[4][4][4];
#pragma unroll
    for (int i = 0; i < 4; i++)
#pragma unroll
        for (int j = 0; j < 4; j++)
#pragma unroll
            for (int r = 0; r < 4; r++) acc[i][j][r] = 0.f;

#pragma unroll
    for (int s = 0; s < 4; s++) {
        gemm_issue_1(Ah, Bh, m0, n0, s, sbase + (uint32_t)s * PSTAGE * 2, tid);
        CP_COMMIT();
    }

    const int a_row = (lane & 15);
    const int a_col = (lane >> 4) << 3;
    const int bq = lane >> 3;
    const int b_row = (lane & 7) + ((bq >> 1) << 3);
    const int b_col = (bq & 1) << 3;

    for (int kc2 = 0; kc2 < 16; kc2++) {
        CP_WAIT2();
        __syncthreads();

#pragma unroll
        for (int half = 0; half < 2; half++) {
            const int sub = 2 * kc2 + half;
            const uint32_t st = sbase + (uint32_t)((sub & 3) * PSTAGE) * 2;
            const uint32_t sAh = st;
            const uint32_t sBh = st + MATST * 2;

#pragma unroll
            for (int kk = 0; kk < 2; kk++) {
                uint32_t ah[4][4], bh[4][2];
#pragma unroll
                for (int mi = 0; mi < 4; mi++) {
                    uint32_t off = (uint32_t)((wm + mi * 16 + a_row) * ROWST + kk * 16 + a_col) * 2;
                    ldsm4(ah[mi], sAh + off);
                }
#pragma unroll
                for (int g = 0; g < 2; g++) {
                    uint32_t off = (uint32_t)((wn + g * 16 + b_row) * ROWST + kk * 16 + b_col) * 2;
                    uint32_t r[4];
                    ldsm4(r, sBh + off);
                    bh[g * 2][0] = r[0]; bh[g * 2][1] = r[1];
                    bh[g * 2 + 1][0] = r[2]; bh[g * 2 + 1][1] = r[3];
                }
#pragma unroll
                for (int mi = 0; mi < 4; mi++)
#pragma unroll
                    for (int ni = 0; ni < 4; ni++)
                        mma16816(acc[mi][ni], ah[mi], bh[ni]);
            }
        }
        __syncthreads();
#pragma unroll
        for (int half = 0; half < 2; half++) {
            const int sub = 2 * kc2 + 4 + half;
            if (sub < 32)
                gemm_issue_1(Ah, Bh, m0, n0, sub,
                             sbase + (uint32_t)((sub & 3) * PSTAGE) * 2, tid);
            CP_COMMIT();
        }
    }

    const int er = lane >> 2;
    const int ec = (lane & 3) * 2;
#pragma unroll
    for (int mi = 0; mi < 4; mi++) {
        const int r0 = m0 + wm + mi * 16 + er;
#pragma unroll
        for (int ni = 0; ni < 4; ni++) {
            const int c = n0 + wn + ni * 8 + ec;
            if (HOUT) {
                __half2 p0 = __floats2half2_rn(acc[mi][ni][0], acc[mi][ni][1]);
                __half2 p1 = __floats2half2_rn(acc[mi][ni][2], acc[mi][ni][3]);
                *(uint32_t*)(Ch + (size_t)r0 * Ff + c)       = *(uint32_t*)&p0;
                *(uint32_t*)(Ch + (size_t)(r0 + 8) * Ff + c) = *(uint32_t*)&p1;
            } else {
                *(float2*)(Cf + (size_t)r0 * Ff + c) =
                    make_float2(acc[mi][ni][0], acc[mi][ni][1]);
                *(float2*)(Cf + (size_t)(r0 + 8) * Ff + c) =
                    make_float2(acc[mi][ni][2], acc[mi][ni][3]);
            }
        }
    }
}

// ---------------------------------------------------------------------------
// LN batched over fp16 inputs: z=0 -> q LN+reshape (x0.125), z=1 -> k
// LN+reshape, z=2 -> v stats only.
// ---------------------------------------------------------------------------
__global__ __launch_bounds__(256)
void ln3(const __half* __restrict__ xq, const __half* __restrict__ xk,
         const __half* __restrict__ xv,
         const float* __restrict__ sq, const float* __restrict__ bq,
         const float* __restrict__ sk, const float* __restrict__ bk,
         __half* __restrict__ QH, __half* __restrict__ KH,
         float2* __restrict__ vstat) {
    __shared__ float red[16];
    const int z = blockIdx.y;
    const int row = blockIdx.x;
    const int b = row >> 10, l = row & 1023;
    const int tid = threadIdx.x;
    const __half* x = (z == 0) ? xq : (z == 1) ? xk : xv;
    const __half* xr = x + (size_t)row * Ff;

    uint2 raw = *(const uint2*)(xr + tid * 4);
    float2 va = __half22float2(*(__half2*)&raw.x);
    float2 vb = __half22float2(*(__half2*)&raw.y);
    float s  = va.x + va.y + vb.x + vb.y;
    float sq2 = va.x * va.x + va.y * va.y + vb.x * vb.x + vb.y * vb.y;
#pragma unroll
    for (int o = 16; o > 0; o >>= 1) {
        s   += __shfl_xor_sync(0xffffffffu, s, o);
        sq2 += __shfl_xor_sync(0xffffffffu, sq2, o);
    }
    const int warp = tid >> 5, lane = tid & 31;
    if (lane == 0) { red[warp] = s; red[warp + 8] = sq2; }
    __syncthreads();
    float st = 0.f, sqt = 0.f;
#pragma unroll
    for (int w = 0; w < 8; w++) { st += red[w]; sqt += red[w + 8]; }

    const float mean = st * (1.0f / Ff);
    const float var  = sqt * (1.0f / Ff) - mean * mean;
    const float inv  = rsqrtf(var + EPS);

    if (z == 2) {
        if (tid == 0) vstat[row] = make_float2(mean, inv);
        return;
    }

    const float* scale = (z == 0) ? sq : sk;
    const float* bias  = (z == 0) ? bq : bk;
    const float qs = (z == 0) ? 0.125f : 1.0f;
    __half* OH = (z == 0) ? QH : KH;

    float4 sc = *(const float4*)(scale + tid * 4);
    float4 bi = *(const float4*)(bias + tid * 4);
    float y0 = ((va.x - mean) * inv * sc.x + bi.x) * qs;
    float y1 = ((va.y - mean) * inv * sc.y + bi.y) * qs;
    float y2 = ((vb.x - mean) * inv * sc.z + bi.z) * qs;
    float y3 = ((vb.y - mean) * inv * sc.w + bi.w) * qs;

    const int col = tid * 4;
    const int h = col >> 6, d = col & 63;
    const size_t o = (((size_t)b * Hh + h) * Ll + l) * Dd + d;
    __half2 ha = __floats2half2_rn(y0, y1);
    __half2 hb = __floats2half2_rn(y2, y3);
    uint2 hu;
    hu.x = *(uint32_t*)&ha; hu.y = *(uint32_t*)&hb;
    *(uint2*)(OH + o) = hu;
}

// ---------------------------------------------------------------------------
// V: apply LN (from stats) + transpose fp16 -> fp16 [B,H,D,L].
// ---------------------------------------------------------------------------
__global__ __launch_bounds__(256)
void vtrans_ln(const __half* __restrict__ V, const float2* __restrict__ vstat,
               const float* __restrict__ sv, const float* __restrict__ bv,
               __half* __restrict__ TH) {
    __shared__ float ts[64][65];
    const int bh = blockIdx.x;
    const int b = bh >> 4, h = bh & 15;
    const int l0 = blockIdx.y * 64;
    const int tid = threadIdx.x;
    {
        const int i = tid >> 2;
        const int c0 = (tid & 3) * 16;
        const float2 stv = vstat[b * Ll + l0 + i];
        const __half* src = V + ((size_t)b * Ll + l0 + i) * Ff + h * Dd + c0;
        const float* gp = sv + h * Dd + c0;
        const float* bp = bv + h * Dd + c0;
#pragma unroll
        for (int j = 0; j < 4; j++) {
            uint2 raw = *(const uint2*)(src + j * 4);
            float2 a0 = __half22float2(*(__half2*)&raw.x);
            float2 a1 = __half22float2(*(__half2*)&raw.y);
            float4 g = *(const float4*)(gp + j * 4);
            float4 be = *(const float4*)(bp + j * 4);
            ts[i][c0 + j * 4 + 0] = (a0.x - stv.x) * stv.y * g.x + be.x;
            ts[i][c0 + j * 4 + 1] = (a0.y - stv.x) * stv.y * g.y + be.y;
            ts[i][c0 + j * 4 + 2] = (a1.x - stv.x) * stv.y * g.z + be.z;
            ts[i][c0 + j * 4 + 3] = (a1.y - stv.x) * stv.y * g.w + be.w;
        }
    }
    __syncthreads();
    {
        const int d = tid >> 2;
        const int lc = (tid & 3) * 16;
        const size_t o = ((size_t)bh * Dd + d) * Ll + l0 + lc;
        __align__(16) __half hs[16];
#pragma unroll
        for (int j = 0; j < 16; j++)
            hs[j] = __float2half(ts[lc + j][d]);
        *(uint4*)(TH + o)     = *(uint4*)(hs);
        *(uint4*)(TH + o + 8) = *(uint4*)(hs + 8);
    }
}

// ---------------------------------------------------------------------------
// Flash attention (mma.sync). QK^T: fp16. PV: pah*vh + pal*vh.
// 2 smem tiles/stage (Kh, Vth). fp16 mask, fp16 output. (R14 version)
// ---------------------------------------------------------------------------
#define FROWS 72
#define FTILE (64 * FROWS)
#define FSTAGE (2 * FTILE)
#define FLASH_SMEM (2 * FSTAGE * 2)

__device__ __forceinline__ void flash_issue(
    const __half* __restrict__ Kh, const __half* __restrict__ Vth,
    int bh, int k0, uint32_t st, int tid) {
    const int row = tid >> 2;
    const int ch = tid & 3;
    const size_t kb = ((size_t)bh * Ll + k0) * Dd;
    const size_t vb = ((size_t)bh * Dd) * Ll + k0;
#pragma unroll
    for (int s = 0; s < 2; s++) {
        const int c8 = ch + s * 4;
        const uint32_t so = (uint32_t)(row * FROWS + c8 * 8) * 2;
        CP_ASYNC16(st + 0 * FTILE * 2 + so, Kh + kb + (size_t)row * Dd + c8 * 8);
        CP_ASYNC16(st + 1 * FTILE * 2 + so, Vth + vb + (size_t)row * Ll + c8 * 8);
    }
}

__global__ __launch_bounds__(256, 2)
void flash_mma(const __half* __restrict__ Qh, const __half* __restrict__ Kh,
               const __half* __restrict__ Vth,
               const __half* __restrict__ maskh,
               __half* __restrict__ Oh) {
    extern __shared__ __align__(16) __half fsm[];
    const int tid = threadIdx.x;
    const int lane = tid & 31;
    const int wid = tid >> 5;
    const int q0 = blockIdx.x * 128;
    const int bh = blockIdx.y;
    const int b = bh >> 4, h = bh & 15;
    const uint32_t sbase = smem_u32(fsm);
    const int wr0 = q0 + wid * 16;
    const int er = lane >> 2;
    const int ec = (lane & 3) * 2;

    uint32_t qfh[4][4];
    {
        const size_t qb = (size_t)bh * Ll * Dd;
        const size_t r0 = qb + (size_t)(wr0 + er) * Dd;
        const size_t r1 = qb + (size_t)(wr0 + er + 8) * Dd;
#pragma unroll
        for (int kk = 0; kk < 4; kk++) {
            const int c0 = kk * 16 + ec, c1 = kk * 16 + ec + 8;
            qfh[kk][0] = *(const uint32_t*)(Qh + r0 + c0);
            qfh[kk][1] = *(const uint32_t*)(Qh + r1 + c0);
            qfh[kk][2] = *(const uint32_t*)(Qh + r0 + c1);
            qfh[kk][3] = *(const uint32_t*)(Qh + r1 + c1);
        }
    }

    float oacc[8][4];
#pragma unroll
    for (int i = 0; i < 8; i++)
#pragma unroll
        for (int j = 0; j < 4; j++) oacc[i][j] = 0.f;
    float lsum0 = 0.f, lsum1 = 0.f;

    flash_issue(Kh, Vth, bh, 0, sbase, tid);
    CP_COMMIT();
    flash_issue(Kh, Vth, bh, 64, sbase + FSTAGE * 2, tid);
    CP_COMMIT();

    const int bq = lane >> 3;
    const int b_row = (lane & 7) + ((bq >> 1) << 3);
    const int b_col = (bq & 1) << 3;

    for (int t = 0; t < 16; t++) {
        CP_WAIT1();
        __syncthreads();
        const uint32_t st = sbase + (uint32_t)((t & 1) * FSTAGE) * 2;
        const uint32_t sKh = st;
        const uint32_t sVh = st + FTILE * 2;

        float sc[8][4];
#pragma unroll
        for (int i = 0; i < 8; i++)
#pragma unroll
            for (int j = 0; j < 4; j++) sc[i][j] = 0.f;

#pragma unroll
        for (int kk = 0; kk < 4; kk++) {
#pragma unroll
            for (int g = 0; g < 4; g++) {
                const uint32_t off = (uint32_t)((g * 16 + b_row) * FROWS + kk * 16 + b_col) * 2;
                uint32_t rh[4];
                ldsm4(rh, sKh + off);
                mma16816(sc[2 * g],     qfh[kk], rh);
                mma16816(sc[2 * g + 1], qfh[kk], rh + 2);
            }
        }

        const int k0 = t * 64;
        uint32_t pah[4][4], pal[4][4];
        const __half* mr0 = maskh + (size_t)(wr0 + er) * Ll + k0 + ec;
        const __half* mr1 = mr0 + 8 * Ll;
#pragma unroll
        for (int ni = 0; ni < 8; ni++) {
            float2 m0 = __half22float2(*(const __half2*)(mr0 + ni * 8));
            float2 m1 = __half22float2(*(const __half2*)(mr1 + ni * 8));
            float p0 = __expf(sc[ni][0] + m0.x);
            float p1 = __expf(sc[ni][1] + m0.y);
            float p2 = __expf(sc[ni][2] + m1.x);
            float p3 = __expf(sc[ni][3] + m1.y);
            lsum0 += p0 + p1;
            lsum1 += p2 + p3;
            __half2 h01 = __floats2half2_rn(p0, p1);
            __half2 h23 = __floats2half2_rn(p2, p3);
            float2 f01 = __half22float2(h01);
            float2 f23 = __half22float2(h23);
            __half2 l01 = __floats2half2_rn(p0 - f01.x, p1 - f01.y);
            __half2 l23 = __floats2half2_rn(p2 - f23.x, p3 - f23.y);
            const int kc = ni >> 1, u = ni & 1;
            pah[kc][u * 2 + 0] = *(uint32_t*)&h01;
            pah[kc][u * 2 + 1] = *(uint32_t*)&h23;
            pal[kc][u * 2 + 0] = *(uint32_t*)&l01;
            pal[kc][u * 2 + 1] = *(uint32_t*)&l23;
        }

#pragma unroll
        for (int kc = 0; kc < 4; kc++) {
#pragma unroll
            for (int g = 0; g < 4; g++) {
                const uint32_t off = (uint32_t)((g * 16 + b_row) * FROWS + kc * 16 + b_col) * 2;
                uint32_t rh[4];
                ldsm4(rh, sVh + off);
                mma16816(oacc[2 * g],     pah[kc], rh);
                mma16816(oacc[2 * g + 1], pah[kc], rh + 2);
                mma16816(oacc[2 * g],     pal[kc], rh);
                mma16816(oacc[2 * g + 1], pal[kc], rh + 2);
            }
        }
        __syncthreads();
        if (t + 2 < 16)
            flash_issue(Kh, Vth, bh, (t + 2) * 64,
                        sbase + (uint32_t)((t & 1) * FSTAGE) * 2, tid);
        CP_COMMIT();
    }

    lsum0 += __shfl_xor_sync(0xffffffffu, lsum0, 1);
    lsum0 += __shfl_xor_sync(0xffffffffu, lsum0, 2);
    lsum1 += __shfl_xor_sync(0xffffffffu, lsum1, 1);
    lsum1 += __shfl_xor_sync(0xffffffffu, lsum1, 2);
    const float inv0 = 1.0f / lsum0;
    const float inv1 = 1.0f / lsum1;

    const size_t ob0 = ((size_t)b * Ll + wr0 + er) * Ff + h * Dd + ec;
    const size_t ob1 = ob0 + (size_t)8 * Ff;
#pragma unroll
    for (int ni = 0; ni < 8; ni++) {
        __half2 h01 = __floats2half2_rn(oacc[ni][0] * inv0, oacc[ni][1] * inv0);
        __half2 h23 = __floats2half2_rn(oacc[ni][2] * inv1, oacc[ni][3] * inv1);
        *(uint32_t*)(Oh + ob0 + ni * 8) = *(uint32_t*)&h01;
        *(uint32_t*)(Oh + ob1 + ni * 8) = *(uint32_t*)&h23;
    }
}

// ---------------------------------------------------------------------------
// Launch
// ---------------------------------------------------------------------------
extern "C" void kernel_launch(void* const* d_in, const int* in_sizes, int n_in,
                              void* d_out, int out_size) {
    const float* kv    = (const float*)d_in[0];
    const float* q     = (const float*)d_in[1];
    const float* mask  = (const float*)d_in[2];
    const float* Wq    = (const float*)d_in[3];
    const float* Wk    = (const float*)d_in[4];
    const float* Wv    = (const float*)d_in[5];
    const float* Wo    = (const float*)d_in[6];
    const float* lnq_s = (const float*)d_in[7];
    const float* lnq_b = (const float*)d_in[8];
    const float* lnk_s = (const float*)d_in[9];
    const float* lnk_b = (const float*)d_in[10];
    const float* lnv_s = (const float*)d_in[11];
    const float* lnv_b = (const float*)d_in[12];
    float* out = (float*)d_out;

    float2* pvstat;
    __half *pcq, *pck, *pcv, *pqh, *pkvh, *pvth, *poh, *pmh, *pwh;
    cudaGetSymbolAddress((void**)&pcq, g_cq);
    cudaGetSymbolAddress((void**)&pck, g_ck);
    cudaGetSymbolAddress((void**)&pcv, g_cv);
    cudaGetSymbolAddress((void**)&pvstat, g_vstat);
    cudaGetSymbolAddress((void**)&pqh, g_qh);
    cudaGetSymbolAddress((void**)&pkvh, g_kvh);
    cudaGetSymbolAddress((void**)&pvth, g_vth);
    cudaGetSymbolAddress((void**)&poh, g_oh);
    cudaGetSymbolAddress((void**)&pmh, g_maskh);
    cudaGetSymbolAddress((void**)&pwh, g_wh);

    cudaFuncSetAttribute(gemm_1p<true>, cudaFuncAttributeMaxDynamicSharedMemorySize,
                         GEMM1_SMEM_BYTES);
    cudaFuncSetAttribute(gemm_1p<false>, cudaFuncAttributeMaxDynamicSharedMemorySize,
                         GEMM1_SMEM_BYTES);
    cudaFuncSetAttribute(flash_mma, cudaFuncAttributeMaxDynamicSharedMemorySize,
                         FLASH_SMEM);

    const int conv_blocks = (MTOT * Ff / 4) / 256;  // 8192

    // 0: q + kv to fp16
    convert_hi2<<<dim3(conv_blocks, 2), 256>>>(q, kv, pqh, pkvh);
    // 1: mask to fp16
    convert_mask<<<(Ll * Ll / 4) / 256, 256>>>(mask, pmh);
    // 2: transpose all weights to fp16
    transpose_hi_all<<<dim3(32, 32, 4), dim3(32, 8)>>>(Wq, Wk, Wv, Wo);
    // 3: QKV projections -> fp16 C
    gemm_1p<true><<<dim3(Ff / 128, MTOT / 128, 3), 256, GEMM1_SMEM_BYTES>>>(
        pqh, pkvh, pkvh, pwh, 0, nullptr, pcq, pck, pcv);
    // 4: LN q/k (+reshape) and V stats (fp16 inputs)
    ln3<<<dim3(MTOT, 3), 256>>>(pcq, pck, pcv, lnq_s, lnq_b, lnk_s, lnk_b,
                                pqh, pkvh, pvstat);
    // 5: V LN-apply + transpose
    vtrans_ln<<<dim3(Bb * Hh, Ll / 64), 256>>>(pcv, pvstat, lnv_s, lnv_b, pvth);
    // 6: attention
    flash_mma<<<dim3(Ll / 128, Bb * Hh), 256, FLASH_SMEM>>>(
        pqh, pkvh, pvth, pmh, poh);
    // 7: output projection -> fp32 out
    gemm_1p<false><<<dim3(Ff / 128, MTOT / 128, 1), 256, GEMM1_SMEM_BYTES>>>(
        poh, poh, poh, pwh, 3, out, nullptr, nullptr, nullptr);
}